// round 4
// baseline (speedup 1.0000x reference)
#include <cuda_runtime.h>

#define CLASSES 21
#define TPB 128          // threads per block
#define APB (2 * TPB)    // anchors per block (ILP2 per thread)
#define TMAXS 256        // max targets held in SMEM (actual T = 200)

// ---------------- global accumulators (scratch via __device__ globals) -------
__device__ double g_cls_sum;
__device__ double g_reg_sum;
__device__ int    g_pos_cnt;

__global__ void rn_init() {
    g_cls_sum = 0.0;
    g_reg_sum = 0.0;
    g_pos_cnt = 0;
}

// smooth L1
__device__ __forceinline__ float sl1(float d) {
    float ad = fabsf(d);
    return (ad < 1.0f) ? 0.5f * ad * ad : ad - 0.5f;
}

// Per-anchor tail: focal loss over 21 classes + regression if positive.
__device__ __forceinline__ void anchor_tail(
    int a, float bi, float bu, int bt,
    const float* __restrict__ cls,
    const float4* __restrict__ box,
    float4 an,
    const float4* s_tb, const int* s_tl,
    float& cls_acc, float& reg_acc, int& pos_acc)
{
    // pos <=> max_iou >= 0.5  (inter/union >= 0.5, union > 0)
    bool pos = (bi >= 0.5f * bu);
    int lbl = pos ? s_tl[bt] : 0;   // background one-hot hits class 0

    const float* cp = cls + (long long)a * CLASSES;

    // Branchless negative-form focal for all classes; remember x at the label.
    float fsum = 0.0f;
    float xl = 0.0f;
#pragma unroll
    for (int c = 0; c < CLASSES; c++) {
        float x = __ldg(cp + c);
        if (c == lbl) xl = x;
        float ax = fabsf(x);
        float e  = __expf(-ax);           // exp(-|x|)
        float d  = 1.0f + e;
        float r  = __fdividef(1.0f, d);   // 1/(1+e)
        float p  = (x >= 0.0f) ? r : e * r;        // sigmoid(x), stable
        float spx = fmaxf(x, 0.0f) + __logf(d);    // softplus(x), stable
        fsum += p * p * spx;              // neg core: p^2 * (-log_sigmoid(-x))
    }
    // Correct the single target=1 class: remove its neg term, add pos term.
    {
        float ax = fabsf(xl);
        float e  = __expf(-ax);
        float d  = 1.0f + e;
        float r  = __fdividef(1.0f, d);
        float p  = (xl >= 0.0f) ? r : e * r;
        float pm = (xl >= 0.0f) ? e * r : r;       // 1 - p, stable
        float spx  = fmaxf(xl, 0.0f) + __logf(d);  // softplus(x)
        float spnx = spx - xl;                     // softplus(-x)
        fsum = 0.75f * (fsum - p * p * spx) + 0.25f * pm * pm * spnx;
    }
    cls_acc += fsum;

    if (pos) {
        float4 bp  = box[a];
        float4 tbv = s_tb[bt];
        float acx = 0.5f * (an.x + an.z), acy = 0.5f * (an.y + an.w);
        float aw  = an.z - an.x,          ah  = an.w - an.y;
        float iaw = __fdividef(1.0f, aw), iah = __fdividef(1.0f, ah);

        float pcx = 0.5f * (bp.x + bp.z), pcy = 0.5f * (bp.y + bp.w);
        float pw  = bp.z - bp.x,          ph  = bp.w - bp.y;
        float tcx = 0.5f * (tbv.x + tbv.z), tcy = 0.5f * (tbv.y + tbv.w);
        float tw  = tbv.z - tbv.x,          th  = tbv.w - tbv.y;

        float d0 = (pcx - acx) * iaw - (tcx - acx) * iaw;
        float d1 = (pcy - acy) * iah - (tcy - acy) * iah;
        float d2 = __logf(pw * iaw) - __logf(tw * iaw);
        float d3 = __logf(ph * iah) - __logf(th * iah);

        reg_acc += sl1(d0) + sl1(d1) + sl1(d2) + sl1(d3);
        pos_acc += 1;
    }
}

__global__ __launch_bounds__(TPB) void rn_loss(
    const float*  __restrict__ cls,
    const float4* __restrict__ box,
    const float4* __restrict__ anc,
    const float4* __restrict__ tb,
    const int*    __restrict__ tl,
    int A, int T)
{
    __shared__ float4 s_tb[TMAXS];
    __shared__ float  s_area[TMAXS];
    __shared__ int    s_tl[TMAXS];
    __shared__ double s_red[TPB];

    const int tid = threadIdx.x;

    for (int t = tid; t < T; t += TPB) {
        float4 b  = tb[t];
        s_tb[t]   = b;
        s_area[t] = (b.z - b.x) * (b.w - b.y);
        s_tl[t]   = tl[t];
    }
    __syncthreads();

    const int a0 = blockIdx.x * APB + tid;
    const int a1 = a0 + TPB;
    const bool v0 = a0 < A, v1 = a1 < A;

    float4 an0 = v0 ? anc[a0] : make_float4(0.f, 0.f, 1e-3f, 1e-3f);
    float4 an1 = v1 ? anc[a1] : make_float4(0.f, 0.f, 1e-3f, 1e-3f);
    float areaB0 = (an0.z - an0.x) * (an0.w - an0.y);
    float areaB1 = (an1.z - an1.x) * (an1.w - an1.y);

    // best (inter, union, idx) per anchor; compare by cross-product (no div)
    float bi0 = 0.f, bu0 = 1.f;  int bt0 = 0;
    float bi1 = 0.f, bu1 = 1.f;  int bt1 = 0;

#pragma unroll 4
    for (int t = 0; t < T; t++) {
        float4 b = s_tb[t];
        float aA = s_area[t];
        {
            float lx = fmaxf(b.x, an0.x), ly = fmaxf(b.y, an0.y);
            float rx = fminf(b.z, an0.z), ry = fminf(b.w, an0.w);
            float w  = fmaxf(rx - lx, 0.f), h = fmaxf(ry - ly, 0.f);
            float inter = w * h;
            float uni   = fmaxf(aA + areaB0 - inter, 1e-8f);
            if (inter * bu0 > bi0 * uni) { bi0 = inter; bu0 = uni; bt0 = t; }
        }
        {
            float lx = fmaxf(b.x, an1.x), ly = fmaxf(b.y, an1.y);
            float rx = fminf(b.z, an1.z), ry = fminf(b.w, an1.w);
            float w  = fmaxf(rx - lx, 0.f), h = fmaxf(ry - ly, 0.f);
            float inter = w * h;
            float uni   = fmaxf(aA + areaB1 - inter, 1e-8f);
            if (inter * bu1 > bi1 * uni) { bi1 = inter; bu1 = uni; bt1 = t; }
        }
    }

    float cls_acc = 0.f, reg_acc = 0.f;
    int   pos_acc = 0;
    if (v0) anchor_tail(a0, bi0, bu0, bt0, cls, box, an0, s_tb, s_tl,
                        cls_acc, reg_acc, pos_acc);
    if (v1) anchor_tail(a1, bi1, bu1, bt1, cls, box, an1, s_tb, s_tl,
                        cls_acc, reg_acc, pos_acc);

    // ---- block reduction (double) ----
    __syncthreads();
    s_red[tid] = (double)cls_acc;
    __syncthreads();
#pragma unroll
    for (int s = TPB / 2; s > 0; s >>= 1) {
        if (tid < s) s_red[tid] += s_red[tid + s];
        __syncthreads();
    }
    if (tid == 0) atomicAdd(&g_cls_sum, s_red[0]);
    __syncthreads();

    s_red[tid] = (double)reg_acc;
    __syncthreads();
#pragma unroll
    for (int s = TPB / 2; s > 0; s >>= 1) {
        if (tid < s) s_red[tid] += s_red[tid + s];
        __syncthreads();
    }
    if (tid == 0) atomicAdd(&g_reg_sum, s_red[0]);
    __syncthreads();

    s_tl[tid] = pos_acc;   // reuse int SMEM for pos-count reduce
    __syncthreads();
#pragma unroll
    for (int s = TPB / 2; s > 0; s >>= 1) {
        if (tid < s) s_tl[tid] += s_tl[tid + s];
        __syncthreads();
    }
    if (tid == 0) atomicAdd(&g_pos_cnt, s_tl[0]);
}

__global__ void rn_finalize(float* out, int n) {
    int pc = g_pos_cnt;
    double norm = (pc < 1) ? 1.0 : (double)pc;
    float wc = (float)(g_cls_sum / norm);
    float wr = (pc > 0) ? (float)(g_reg_sum / (norm * 4.0)) : 0.0f;
    if (n > 0) out[0] = wc + wr;
    if (n > 1) out[1] = wc;
    if (n > 2) out[2] = wr;
}

extern "C" void kernel_launch(void* const* d_in, const int* in_sizes, int n_in,
                              void* d_out, int out_size) {
    const float*  cls = (const float*)d_in[0];
    const float4* box = (const float4*)d_in[1];
    const float4* anc = (const float4*)d_in[2];
    const float4* tb  = (const float4*)d_in[3];
    const int*    tl  = (const int*)d_in[4];

    int A = in_sizes[0] / CLASSES;   // flattened anchor count
    int T = in_sizes[4];             // flattened target count (<= TMAXS)
    if (T > TMAXS) T = TMAXS;

    rn_init<<<1, 1>>>();
    int grid = (A + APB - 1) / APB;
    rn_loss<<<grid, TPB>>>(cls, box, anc, tb, tl, A, T);
    rn_finalize<<<1, 1>>>((float*)d_out, out_size);
}